// round 12
// baseline (speedup 1.0000x reference)
#include <cuda_runtime.h>
#include <cuda_fp16.h>
#include <cstdint>

#define D      64
#define NROWS  8192
#define BM     256
#define BN     256
#define GAMMA  0.015625f
#define LOG2E  1.4426950408889634f
#define TWOGL  (0.03125f * LOG2E)

// ---------------- device scratch: fp16 fragment-layout inputs ----------------
// A (m16n8k16): value(r,k) -> grp=r>>4, chunk=k>>4, lane=(r&7)*4+((k&7)>>1),
//               reg=((r>>3)&1)+2*((k>>3)&1), half=k&1
// B: col-permuted (perm16); value(j,k) -> grp=(j>>4)*2+(p>>3), col=p&7,
//               pair=k>>5, word=((k>>4)&1)*2+((k>>3)&1), lane=col*4+((k&7)>>1)
__device__ float g_xs[NROWS];   // -gamma*log2e*||x||^2
__device__ float g_ys[NROWS];
__device__ __align__(16) __half g_Af[NROWS * D];
__device__ __align__(16) __half g_Bf[NROWS * D];

// ---------------- prep: half2-paired fragment scatter + scaled norms --------
__global__ void __launch_bounds__(256)
prep_kernel(const float* __restrict__ A, const float* __restrict__ B,
            int rows_each) {
    int half = gridDim.x >> 1;
    int bid  = blockIdx.x;
    bool isB = bid >= half;
    if (isB) bid -= half;

    int w    = bid * 8 + (threadIdx.x >> 5);
    int lane = threadIdx.x & 31;       // handles k = 2*lane, 2*lane+1
    if (w >= rows_each) return;

    float2 f = reinterpret_cast<const float2*>((isB ? B : A) + (size_t)w * D)[lane];
    __half2 h = __floats2half2_rn(f.x, f.y);

    if (!isB) {
        int grp  = w >> 4;
        int chnk = lane >> 3;
        int ln   = (w & 7) * 4 + (lane & 3);
        int reg  = ((w >> 3) & 1) + 2 * ((lane >> 2) & 1);
        reinterpret_cast<__half2*>(g_Af)[((grp * 4 + chnk) * 32 + ln) * 4 + reg] = h;
    } else {
        int w16  = w & 15;
        int p    = 2 * (w16 >> 2) + (w16 & 1) + 8 * ((w16 >> 1) & 1); // inv perm16
        int grp  = (w >> 4) * 2 + (p >> 3);
        int ln   = (p & 7) * 4 + (lane & 3);
        int pair = lane >> 4;
        int wrd  = ((lane >> 3) & 1) * 2 + ((lane >> 2) & 1);
        reinterpret_cast<__half2*>(g_Bf)[((grp * 2 + pair) * 32 + ln) * 4 + wrd] = h;
    }

    float s = f.x * f.x + f.y * f.y;   // norms from exact f32
#pragma unroll
    for (int o = 16; o; o >>= 1) s += __shfl_xor_sync(0xffffffffu, s, o);
    if (lane == 0) (isB ? g_ys : g_xs)[w] = -(GAMMA * LOG2E) * s;
}

// ---------------- fp16 mma / ex2 helpers ----------------
__device__ __forceinline__ void mma_f16(float* d, const uint32_t* a,
                                        const uint32_t* b) {
    asm volatile(
        "mma.sync.aligned.m16n8k16.row.col.f32.f16.f16.f32 "
        "{%0,%1,%2,%3}, {%4,%5,%6,%7}, {%8,%9}, {%0,%1,%2,%3};"
        : "+f"(d[0]), "+f"(d[1]), "+f"(d[2]), "+f"(d[3])
        : "r"(a[0]), "r"(a[1]), "r"(a[2]), "r"(a[3]), "r"(b[0]), "r"(b[1]));
}
__device__ __forceinline__ float epi(float acc, float xy) {
    float r = fminf(fmaf(TWOGL, acc, xy), 0.f);
    asm("ex2.approx.f32 %0, %1;" : "=f"(r) : "f"(r));
    return r;
}

// ---------------- main: fp16 HMMA, 128x64 warp tile, A prefetch -----------
__global__ void __launch_bounds__(256, 2)
rbf_f16_kernel(float* __restrict__ out, int N) {
    const int tid  = threadIdx.x;
    const int lane = tid & 31;
    const int wid  = tid >> 5;
    const int gID  = lane >> 2;
    const int tig  = lane & 3;
    const int wm   = wid >> 2;    // 0..1 : 128-row slab
    const int wn   = wid & 3;     // 0..3 : 64-col slab
    const int row0 = blockIdx.y * BM;
    const int col0 = blockIdx.x * BN;

    const uint4* Af = reinterpret_cast<const uint4*>(g_Af);
    const uint4* Bf = reinterpret_cast<const uint4*>(g_Bf);

    // ---- hoist ALL B fragments for this warp's 64-col slab (16 LDG.128) ----
    uint4 bf[16];   // [group(8 cols)][chunk-pair(32 k)]
    {
        const int bgrp0 = (col0 >> 3) + wn * 8;
#pragma unroll
        for (int g = 0; g < 8; g++)
#pragma unroll
            for (int p = 0; p < 2; p++)
                bf[g * 2 + p] = Bf[(size_t)(((bgrp0 + g) * 2 + p) * 32 + lane)];
    }
    const uint32_t* bw = reinterpret_cast<const uint32_t*>(bf);

    // ---- hoist ys (same across all mt) ----
    float4 ys4[4];
#pragma unroll
    for (int pr = 0; pr < 4; pr++)
        ys4[pr] = *reinterpret_cast<const float4*>(
            &g_ys[col0 + wn * 64 + pr * 16 + 4 * tig]);

    const int agrp0 = (row0 >> 4) + wm * 8;

    // ---- A double buffer: prefetch chunk mt+1 during chunk mt ----
    uint4 afA[4], afB[4];
#pragma unroll
    for (int c = 0; c < 4; c++)
        afA[c] = Af[(size_t)((agrp0 * 4 + c) * 32 + lane)];

#pragma unroll
    for (int mt = 0; mt < 8; mt++) {
        uint4* cur = (mt & 1) ? afB : afA;
        uint4* nxt = (mt & 1) ? afA : afB;
        if (mt < 7) {
#pragma unroll
            for (int c = 0; c < 4; c++)
                nxt[c] = Af[(size_t)(((agrp0 + mt + 1) * 4 + c) * 32 + lane)];
        }
        const uint32_t* aw = reinterpret_cast<const uint32_t*>(cur);

        const int rbase = row0 + wm * 128 + mt * 16 + gID;
        const float xs0 = g_xs[rbase];
        const float xs1 = g_xs[rbase + 8];

#pragma unroll
        for (int pr = 0; pr < 4; pr++) {
            float accE[4] = {0.f, 0.f, 0.f, 0.f};
            float accO[4] = {0.f, 0.f, 0.f, 0.f};
#pragma unroll
            for (int c = 0; c < 4; c++) {   // 4 k-chunks of 16
                const uint32_t* a  = aw + c * 4;
                const uint32_t* bE =
                    bw + ((2 * pr) * 2 + (c >> 1)) * 4 + (c & 1) * 2;
                const uint32_t* bO =
                    bw + ((2 * pr + 1) * 2 + (c >> 1)) * 4 + (c & 1) * 2;
                mma_f16(accE, a, bE);
                mma_f16(accO, a, bO);
            }
            const int c = col0 + wn * 64 + pr * 16 + 4 * tig;
            float4 v0, v1;
            v0.x = epi(accE[0], xs0 + ys4[pr].x);
            v0.y = epi(accE[1], xs0 + ys4[pr].y);
            v0.z = epi(accO[0], xs0 + ys4[pr].z);
            v0.w = epi(accO[1], xs0 + ys4[pr].w);
            v1.x = epi(accE[2], xs1 + ys4[pr].x);
            v1.y = epi(accE[3], xs1 + ys4[pr].y);
            v1.z = epi(accO[2], xs1 + ys4[pr].z);
            v1.w = epi(accO[3], xs1 + ys4[pr].w);
            __stcs(reinterpret_cast<float4*>(out + (size_t)rbase * N + c), v0);
            __stcs(reinterpret_cast<float4*>(out + (size_t)(rbase + 8) * N + c), v1);
        }
    }
}

// ---------------------------------------------------------------------------
extern "C" void kernel_launch(void* const* d_in, const int* in_sizes, int n_in,
                              void* d_out, int out_size) {
    const float* A = (const float*)d_in[0];  // data        [M, 64]
    const float* B = (const float*)d_in[1];  // support_vec [N, 64]
    float* out     = (float*)d_out;          // [M, N]

    const int M = in_sizes[0] / D;           // 8192
    const int N = in_sizes[1] / D;           // 8192

    prep_kernel<<<(M + 7) / 8 * 2, 256>>>(A, B, M);

    dim3 grid(N / BN, M / BM);
    rbf_f16_kernel<<<grid, 256>>>(out, N);
}

// round 13
// speedup vs baseline: 1.0292x; 1.0292x over previous
#include <cuda_runtime.h>
#include <cuda_fp16.h>
#include <cstdint>

#define D      64
#define NROWS  8192
#define BM     128
#define BN     256
#define GAMMA  0.015625f
#define LOG2E  1.4426950408889634f
#define TWOGL  (0.03125f * LOG2E)

// ---------------- device scratch: fp16 fragment-layout inputs ----------------
// A (m16n8k16): value(r,k) -> grp=r>>4, chunk=k>>4, lane=(r&7)*4+((k&7)>>1),
//               reg=((r>>3)&1)+2*((k>>3)&1), half=k&1
// B: col-permuted (perm16); value(j,k) -> grp=(j>>4)*2+(p>>3), col=p&7,
//               pair=k>>5, word=((k>>4)&1)*2+((k>>3)&1), lane=col*4+((k&7)>>1)
__device__ float g_xs[NROWS];   // -gamma*log2e*||x||^2
__device__ float g_ys[NROWS];
__device__ __align__(16) __half g_Af[NROWS * D];
__device__ __align__(16) __half g_Bf[NROWS * D];

// ---------------- prep: 4 rows/warp (MLP=4), fragment scatter + norms -------
__global__ void __launch_bounds__(256)
prep_kernel(const float* __restrict__ A, const float* __restrict__ B,
            int rows_each) {
    int half = gridDim.x >> 1;
    int bid  = blockIdx.x;
    bool isB = bid >= half;
    if (isB) bid -= half;

    const int w0   = bid * 32 + (threadIdx.x >> 5) * 4;   // 4 rows per warp
    const int lane = threadIdx.x & 31;                    // k-pair 2*lane,2*lane+1
    const float* src = isB ? B : A;

    float2 f[4];
#pragma unroll
    for (int i = 0; i < 4; i++)
        f[i] = reinterpret_cast<const float2*>(src + (size_t)(w0 + i) * D)[lane];

#pragma unroll
    for (int i = 0; i < 4; i++) {
        __half2 h = __floats2half2_rn(f[i].x, f[i].y);
        int w = w0 + i;
        if (!isB) {
            int grp  = w >> 4;
            int chnk = lane >> 3;
            int ln   = (w & 7) * 4 + (lane & 3);
            int reg  = ((w >> 3) & 1) + 2 * ((lane >> 2) & 1);
            reinterpret_cast<__half2*>(g_Af)[((grp * 4 + chnk) * 32 + ln) * 4 + reg] = h;
        } else {
            int w16  = w & 15;
            int p    = 2 * (w16 >> 2) + (w16 & 1) + 8 * ((w16 >> 1) & 1); // inv perm16
            int grp  = (w >> 4) * 2 + (p >> 3);
            int ln   = (p & 7) * 4 + (lane & 3);
            int pair = lane >> 4;
            int wrd  = ((lane >> 3) & 1) * 2 + ((lane >> 2) & 1);
            reinterpret_cast<__half2*>(g_Bf)[((grp * 2 + pair) * 32 + ln) * 4 + wrd] = h;
        }
    }

    float s[4];
#pragma unroll
    for (int i = 0; i < 4; i++) s[i] = f[i].x * f[i].x + f[i].y * f[i].y;
#pragma unroll
    for (int o = 16; o; o >>= 1)
#pragma unroll
        for (int i = 0; i < 4; i++)
            s[i] += __shfl_xor_sync(0xffffffffu, s[i], o);
    if (lane < 4) {
        float* nrm = isB ? g_ys : g_xs;
        nrm[w0 + lane] = -(GAMMA * LOG2E) * s[lane];
    }
}

// ---------------- fp16 mma / ex2 helpers ----------------
__device__ __forceinline__ void mma_f16(float* d, const uint32_t* a,
                                        const uint32_t* b) {
    asm volatile(
        "mma.sync.aligned.m16n8k16.row.col.f32.f16.f16.f32 "
        "{%0,%1,%2,%3}, {%4,%5,%6,%7}, {%8,%9}, {%0,%1,%2,%3};"
        : "+f"(d[0]), "+f"(d[1]), "+f"(d[2]), "+f"(d[3])
        : "r"(a[0]), "r"(a[1]), "r"(a[2]), "r"(a[3]), "r"(b[0]), "r"(b[1]));
}
// no clamp: d2 >= 0 analytically and min pairwise d2 >> fp16 dot error here,
// so exponent is always < 0; matches reference within fp16 quantization.
__device__ __forceinline__ float epi(float acc, float xy) {
    float r = fmaf(TWOGL, acc, xy);
    asm("ex2.approx.f32 %0, %1;" : "=f"(r) : "f"(r));
    return r;
}

// ---------------- main: fp16 HMMA, 64x64 warp tile, 2 CTA/SM --------------
__global__ void __launch_bounds__(256, 2)
rbf_f16_kernel(float* __restrict__ out, int N) {
    const int tid  = threadIdx.x;
    const int lane = tid & 31;
    const int wid  = tid >> 5;
    const int gID  = lane >> 2;
    const int tig  = lane & 3;
    const int wm   = wid >> 2;    // 0..1 : 64-row slab
    const int wn   = wid & 3;     // 0..3 : 64-col slab
    const int row0 = blockIdx.y * BM;
    const int col0 = blockIdx.x * BN;

    const uint4* Af = reinterpret_cast<const uint4*>(g_Af);
    const uint4* Bf = reinterpret_cast<const uint4*>(g_Bf);

    // ---- hoist ALL B fragments for this warp's 64-col slab (16 LDG.128) ----
    uint4 bf[16];   // [group(8 cols)][chunk-pair(32 k)]
    {
        const int bgrp0 = (col0 >> 3) + wn * 8;
#pragma unroll
        for (int g = 0; g < 8; g++)
#pragma unroll
            for (int p = 0; p < 2; p++)
                bf[g * 2 + p] = Bf[(size_t)(((bgrp0 + g) * 2 + p) * 32 + lane)];
    }
    const uint32_t* bw = reinterpret_cast<const uint32_t*>(bf);

    // ---- hoist ys (same across all mt) ----
    float4 ys4[4];
#pragma unroll
    for (int pr = 0; pr < 4; pr++)
        ys4[pr] = *reinterpret_cast<const float4*>(
            &g_ys[col0 + wn * 64 + pr * 16 + 4 * tig]);

#pragma unroll
    for (int mt = 0; mt < 4; mt++) {
        // A fragments for this 16-row group (4 LDG.128)
        uint4 af[4];
        const int agrp = (row0 >> 4) + wm * 4 + mt;
#pragma unroll
        for (int c = 0; c < 4; c++)
            af[c] = Af[(size_t)((agrp * 4 + c) * 32 + lane)];
        const uint32_t* aw = reinterpret_cast<const uint32_t*>(af);

        const int rbase = row0 + wm * 64 + mt * 16 + gID;
        const float xs0 = g_xs[rbase];
        const float xs1 = g_xs[rbase + 8];

#pragma unroll
        for (int pr = 0; pr < 4; pr++) {
            float accE[4] = {0.f, 0.f, 0.f, 0.f};
            float accO[4] = {0.f, 0.f, 0.f, 0.f};
#pragma unroll
            for (int c = 0; c < 4; c++) {   // 4 k-chunks of 16
                const uint32_t* a  = aw + c * 4;
                const uint32_t* bE =
                    bw + ((2 * pr) * 2 + (c >> 1)) * 4 + (c & 1) * 2;
                const uint32_t* bO =
                    bw + ((2 * pr + 1) * 2 + (c >> 1)) * 4 + (c & 1) * 2;
                mma_f16(accE, a, bE);
                mma_f16(accO, a, bO);
            }
            const int c = col0 + wn * 64 + pr * 16 + 4 * tig;
            float4 v0, v1;
            v0.x = epi(accE[0], xs0 + ys4[pr].x);
            v0.y = epi(accE[1], xs0 + ys4[pr].y);
            v0.z = epi(accO[0], xs0 + ys4[pr].z);
            v0.w = epi(accO[1], xs0 + ys4[pr].w);
            v1.x = epi(accE[2], xs1 + ys4[pr].x);
            v1.y = epi(accE[3], xs1 + ys4[pr].y);
            v1.z = epi(accO[2], xs1 + ys4[pr].z);
            v1.w = epi(accO[3], xs1 + ys4[pr].w);
            __stcs(reinterpret_cast<float4*>(out + (size_t)rbase * N + c), v0);
            __stcs(reinterpret_cast<float4*>(out + (size_t)(rbase + 8) * N + c), v1);
        }
    }
}

// ---------------------------------------------------------------------------
extern "C" void kernel_launch(void* const* d_in, const int* in_sizes, int n_in,
                              void* d_out, int out_size) {
    const float* A = (const float*)d_in[0];  // data        [M, 64]
    const float* B = (const float*)d_in[1];  // support_vec [N, 64]
    float* out     = (float*)d_out;          // [M, N]

    const int M = in_sizes[0] / D;           // 8192
    const int N = in_sizes[1] / D;           // 8192

    prep_kernel<<<(M + 31) / 32 * 2, 256>>>(A, B, M);

    dim3 grid(N / BN, M / BM);
    rbf_f16_kernel<<<grid, 256>>>(out, N);
}

// round 14
// speedup vs baseline: 1.0549x; 1.0250x over previous
#include <cuda_runtime.h>
#include <cuda_fp16.h>
#include <cstdint>

#define D      64
#define NROWS  8192
#define BM     128
#define BN     256
#define GAMMA  0.015625f
#define LOG2E  1.4426950408889634f
#define TWOGL  (0.03125f * LOG2E)

// ---------------- device scratch: fp16 fragment-layout inputs ----------------
// A (m16n8k16): value(r,k) -> grp=r>>4, chunk=k>>4, lane=(r&7)*4+((k&7)>>1),
//               reg=((r>>3)&1)+2*((k>>3)&1), half=k&1
// B: col-permuted (perm16); value(j,k) -> grp=(j>>4)*2+(p>>3), col=p&7,
//               pair=k>>5, word=((k>>4)&1)*2+((k>>3)&1), lane=col*4+((k&7)>>1)
__device__ float g_xs[NROWS];   // -gamma*log2e*||x||^2
__device__ float g_ys[NROWS];
__device__ __align__(16) __half g_Af[NROWS * D];
__device__ __align__(16) __half g_Bf[NROWS * D];

// ---------------- prep: 4 rows/warp (MLP=4), fragment scatter + norms -------
__global__ void __launch_bounds__(256)
prep_kernel(const float* __restrict__ A, const float* __restrict__ B,
            int rows_each) {
    int half = gridDim.x >> 1;
    int bid  = blockIdx.x;
    bool isB = bid >= half;
    if (isB) bid -= half;

    const int w0   = bid * 32 + (threadIdx.x >> 5) * 4;   // 4 rows per warp
    const int lane = threadIdx.x & 31;                    // k-pair 2*lane,2*lane+1
    const float* src = isB ? B : A;

    float2 f[4];
#pragma unroll
    for (int i = 0; i < 4; i++)
        f[i] = reinterpret_cast<const float2*>(src + (size_t)(w0 + i) * D)[lane];

#pragma unroll
    for (int i = 0; i < 4; i++) {
        __half2 h = __floats2half2_rn(f[i].x, f[i].y);
        int w = w0 + i;
        if (!isB) {
            int grp  = w >> 4;
            int chnk = lane >> 3;
            int ln   = (w & 7) * 4 + (lane & 3);
            int reg  = ((w >> 3) & 1) + 2 * ((lane >> 2) & 1);
            reinterpret_cast<__half2*>(g_Af)[((grp * 4 + chnk) * 32 + ln) * 4 + reg] = h;
        } else {
            int w16  = w & 15;
            int p    = 2 * (w16 >> 2) + (w16 & 1) + 8 * ((w16 >> 1) & 1); // inv perm16
            int grp  = (w >> 4) * 2 + (p >> 3);
            int ln   = (p & 7) * 4 + (lane & 3);
            int pair = lane >> 4;
            int wrd  = ((lane >> 3) & 1) * 2 + ((lane >> 2) & 1);
            reinterpret_cast<__half2*>(g_Bf)[((grp * 2 + pair) * 32 + ln) * 4 + wrd] = h;
        }
    }

    float s[4];
#pragma unroll
    for (int i = 0; i < 4; i++) s[i] = f[i].x * f[i].x + f[i].y * f[i].y;
#pragma unroll
    for (int o = 16; o; o >>= 1)
#pragma unroll
        for (int i = 0; i < 4; i++)
            s[i] += __shfl_xor_sync(0xffffffffu, s[i], o);
    if (lane < 4) {
        float* nrm = isB ? g_ys : g_xs;
        nrm[w0 + lane] = -(GAMMA * LOG2E) * s[lane];
    }
}

// ---------------- fp16 mma / ex2 helpers ----------------
__device__ __forceinline__ void mma_f16(float* d, const uint32_t* a,
                                        const uint32_t* b) {
    asm volatile(
        "mma.sync.aligned.m16n8k16.row.col.f32.f16.f16.f32 "
        "{%0,%1,%2,%3}, {%4,%5,%6,%7}, {%8,%9}, {%0,%1,%2,%3};"
        : "+f"(d[0]), "+f"(d[1]), "+f"(d[2]), "+f"(d[3])
        : "r"(a[0]), "r"(a[1]), "r"(a[2]), "r"(a[3]), "r"(b[0]), "r"(b[1]));
}
// no clamp: d2 >= 0 analytically and min pairwise d2 >> fp16 dot error here,
// so exponent is always < 0; matches reference within fp16 quantization.
__device__ __forceinline__ float epi(float acc, float xy) {
    float r = fmaf(TWOGL, acc, xy);
    asm("ex2.approx.f32 %0, %1;" : "=f"(r) : "f"(r));
    return r;
}

// ---------------- main: fp16 HMMA, 64x64 warp tile, 2 CTA/SM --------------
__global__ void __launch_bounds__(256, 2)
rbf_f16_kernel(float* __restrict__ out, int N) {
    const int tid  = threadIdx.x;
    const int lane = tid & 31;
    const int wid  = tid >> 5;
    const int gID  = lane >> 2;
    const int tig  = lane & 3;
    const int wm   = wid >> 2;    // 0..1 : 64-row slab
    const int wn   = wid & 3;     // 0..3 : 64-col slab
    const int row0 = blockIdx.y * BM;
    const int col0 = blockIdx.x * BN;

    const uint4* Af = reinterpret_cast<const uint4*>(g_Af);
    const uint4* Bf = reinterpret_cast<const uint4*>(g_Bf);

    // ---- hoist ALL B fragments for this warp's 64-col slab (16 LDG.128) ----
    uint4 bf[16];   // [group(8 cols)][chunk-pair(32 k)]
    {
        const int bgrp0 = (col0 >> 3) + wn * 8;
#pragma unroll
        for (int g = 0; g < 8; g++)
#pragma unroll
            for (int p = 0; p < 2; p++)
                bf[g * 2 + p] = Bf[(size_t)(((bgrp0 + g) * 2 + p) * 32 + lane)];
    }
    const uint32_t* bw = reinterpret_cast<const uint32_t*>(bf);

    // ---- hoist ys (same across all mt) ----
    float4 ys4[4];
#pragma unroll
    for (int pr = 0; pr < 4; pr++)
        ys4[pr] = *reinterpret_cast<const float4*>(
            &g_ys[col0 + wn * 64 + pr * 16 + 4 * tig]);

#pragma unroll
    for (int mt = 0; mt < 4; mt++) {
        // A fragments for this 16-row group (4 LDG.128)
        uint4 af[4];
        const int agrp = (row0 >> 4) + wm * 4 + mt;
#pragma unroll
        for (int c = 0; c < 4; c++)
            af[c] = Af[(size_t)((agrp * 4 + c) * 32 + lane)];
        const uint32_t* aw = reinterpret_cast<const uint32_t*>(af);

        const int rbase = row0 + wm * 64 + mt * 16 + gID;
        const float xs0 = g_xs[rbase];
        const float xs1 = g_xs[rbase + 8];

#pragma unroll
        for (int pr = 0; pr < 4; pr++) {
            float accE[4] = {0.f, 0.f, 0.f, 0.f};
            float accO[4] = {0.f, 0.f, 0.f, 0.f};
#pragma unroll
            for (int c = 0; c < 4; c++) {   // 4 k-chunks of 16
                const uint32_t* a  = aw + c * 4;
                const uint32_t* bE =
                    bw + ((2 * pr) * 2 + (c >> 1)) * 4 + (c & 1) * 2;
                const uint32_t* bO =
                    bw + ((2 * pr + 1) * 2 + (c >> 1)) * 4 + (c & 1) * 2;
                mma_f16(accE, a, bE);
                mma_f16(accO, a, bO);
            }
            const int c = col0 + wn * 64 + pr * 16 + 4 * tig;
            float4 v0, v1;
            v0.x = epi(accE[0], xs0 + ys4[pr].x);
            v0.y = epi(accE[1], xs0 + ys4[pr].y);
            v0.z = epi(accO[0], xs0 + ys4[pr].z);
            v0.w = epi(accO[1], xs0 + ys4[pr].w);
            v1.x = epi(accE[2], xs1 + ys4[pr].x);
            v1.y = epi(accE[3], xs1 + ys4[pr].y);
            v1.z = epi(accO[2], xs1 + ys4[pr].z);
            v1.w = epi(accO[3], xs1 + ys4[pr].w);
            __stcs(reinterpret_cast<float4*>(out + (size_t)rbase * N + c), v0);
            __stcs(reinterpret_cast<float4*>(out + (size_t)(rbase + 8) * N + c), v1);
        }
    }
}

// ---------------------------------------------------------------------------
extern "C" void kernel_launch(void* const* d_in, const int* in_sizes, int n_in,
                              void* d_out, int out_size) {
    const float* A = (const float*)d_in[0];  // data        [M, 64]
    const float* B = (const float*)d_in[1];  // support_vec [N, 64]
    float* out     = (float*)d_out;          // [M, N]

    const int M = in_sizes[0] / D;           // 8192
    const int N = in_sizes[1] / D;           // 8192

    prep_kernel<<<(M + 31) / 32 * 2, 256>>>(A, B, M);

    dim3 grid(N / BN, M / BM);
    rbf_f16_kernel<<<grid, 256>>>(out, N);
}

// round 15
// speedup vs baseline: 1.1141x; 1.0561x over previous
#include <cuda_runtime.h>
#include <cuda_fp16.h>
#include <cstdint>

#define D      64
#define NROWS  8192
#define BM     128
#define BN     256
#define GAMMA  0.015625f
#define LOG2E  1.4426950408889634f
#define TWOGL  (0.03125f * LOG2E)

// ---------------- device scratch: fp16 fragment-layout inputs ----------------
// A (m16n8k16): value(r,k) -> grp=r>>4, chunk=k>>4, lane=(r&7)*4+((k&7)>>1),
//               reg=((r>>3)&1)+2*((k>>3)&1), half=k&1
// B: col-permuted (perm16); value(j,k) -> grp=(j>>4)*2+(p>>3), col=p&7,
//               pair=k>>5, word=((k>>4)&1)*2+((k>>3)&1), lane=col*4+((k&7)>>1)
__device__ float g_xs[NROWS];   // -gamma*log2e*||x||^2
__device__ float g_ys[NROWS];
__device__ __align__(16) __half g_Af[NROWS * D];
__device__ __align__(16) __half g_Bf[NROWS * D];

// ---------------- prep: 4 rows/warp (MLP=4), fragment scatter + norms -------
__global__ void __launch_bounds__(256)
prep_kernel(const float* __restrict__ A, const float* __restrict__ B,
            int rows_each) {
    int half = gridDim.x >> 1;
    int bid  = blockIdx.x;
    bool isB = bid >= half;
    if (isB) bid -= half;

    const int w0   = bid * 32 + (threadIdx.x >> 5) * 4;   // 4 rows per warp
    const int lane = threadIdx.x & 31;                    // k-pair 2*lane,2*lane+1
    const float* src = isB ? B : A;

    float2 f[4];
#pragma unroll
    for (int i = 0; i < 4; i++)
        f[i] = reinterpret_cast<const float2*>(src + (size_t)(w0 + i) * D)[lane];

#pragma unroll
    for (int i = 0; i < 4; i++) {
        __half2 h = __floats2half2_rn(f[i].x, f[i].y);
        int w = w0 + i;
        if (!isB) {
            int grp  = w >> 4;
            int chnk = lane >> 3;
            int ln   = (w & 7) * 4 + (lane & 3);
            int reg  = ((w >> 3) & 1) + 2 * ((lane >> 2) & 1);
            reinterpret_cast<__half2*>(g_Af)[((grp * 4 + chnk) * 32 + ln) * 4 + reg] = h;
        } else {
            int w16  = w & 15;
            int p    = 2 * (w16 >> 2) + (w16 & 1) + 8 * ((w16 >> 1) & 1); // inv perm16
            int grp  = (w >> 4) * 2 + (p >> 3);
            int ln   = (p & 7) * 4 + (lane & 3);
            int pair = lane >> 4;
            int wrd  = ((lane >> 3) & 1) * 2 + ((lane >> 2) & 1);
            reinterpret_cast<__half2*>(g_Bf)[((grp * 2 + pair) * 32 + ln) * 4 + wrd] = h;
        }
    }

    float s[4];
#pragma unroll
    for (int i = 0; i < 4; i++) s[i] = f[i].x * f[i].x + f[i].y * f[i].y;
#pragma unroll
    for (int o = 16; o; o >>= 1)
#pragma unroll
        for (int i = 0; i < 4; i++)
            s[i] += __shfl_xor_sync(0xffffffffu, s[i], o);
    if (lane < 4) {
        float* nrm = isB ? g_ys : g_xs;
        nrm[w0 + lane] = -(GAMMA * LOG2E) * s[lane];
    }
}

// ---------------- fp16 mma / ex2 helpers ----------------
__device__ __forceinline__ void mma_f16(float* d, const uint32_t* a,
                                        const uint32_t* b) {
    asm volatile(
        "mma.sync.aligned.m16n8k16.row.col.f32.f16.f16.f32 "
        "{%0,%1,%2,%3}, {%4,%5,%6,%7}, {%8,%9}, {%0,%1,%2,%3};"
        : "+f"(d[0]), "+f"(d[1]), "+f"(d[2]), "+f"(d[3])
        : "r"(a[0]), "r"(a[1]), "r"(a[2]), "r"(a[3]), "r"(b[0]), "r"(b[1]));
}
__device__ __forceinline__ float epi(float acc, float xy) {
    float r = fminf(fmaf(TWOGL, acc, xy), 0.f);
    asm("ex2.approx.f32 %0, %1;" : "=f"(r) : "f"(r));
    return r;
}

// ---------------- main: fp16 HMMA, 64x64 warp tile, 2 CTA/SM (R9 verbatim) --
__global__ void __launch_bounds__(256, 2)
rbf_f16_kernel(float* __restrict__ out, int N) {
    const int tid  = threadIdx.x;
    const int lane = tid & 31;
    const int wid  = tid >> 5;
    const int gID  = lane >> 2;
    const int tig  = lane & 3;
    const int wm   = wid >> 2;    // 0..1 : 64-row slab
    const int wn   = wid & 3;     // 0..3 : 64-col slab
    const int row0 = blockIdx.y * BM;
    const int col0 = blockIdx.x * BN;

    const uint4* Af = reinterpret_cast<const uint4*>(g_Af);
    const uint4* Bf = reinterpret_cast<const uint4*>(g_Bf);

    // ---- hoist ALL B fragments for this warp's 64-col slab (16 LDG.128) ----
    uint4 bf[16];   // [group(8 cols)][chunk-pair(32 k)]
    {
        const int bgrp0 = (col0 >> 3) + wn * 8;
#pragma unroll
        for (int g = 0; g < 8; g++)
#pragma unroll
            for (int p = 0; p < 2; p++)
                bf[g * 2 + p] = Bf[(size_t)(((bgrp0 + g) * 2 + p) * 32 + lane)];
    }
    const uint32_t* bw = reinterpret_cast<const uint32_t*>(bf);

#pragma unroll
    for (int mt = 0; mt < 4; mt++) {
        // A fragments for this 16-row group (4 LDG.128)
        uint4 af[4];
        const int agrp = (row0 >> 4) + wm * 4 + mt;
#pragma unroll
        for (int c = 0; c < 4; c++)
            af[c] = Af[(size_t)((agrp * 4 + c) * 32 + lane)];
        const uint32_t* aw = reinterpret_cast<const uint32_t*>(af);

        const int rbase = row0 + wm * 64 + mt * 16 + gID;
        const float xs0 = g_xs[rbase];
        const float xs1 = g_xs[rbase + 8];

#pragma unroll
        for (int pr = 0; pr < 4; pr++) {
            float accE[4] = {0.f, 0.f, 0.f, 0.f};
            float accO[4] = {0.f, 0.f, 0.f, 0.f};
#pragma unroll
            for (int c = 0; c < 4; c++) {   // 4 k-chunks of 16
                const uint32_t* a  = aw + c * 4;
                const uint32_t* bE =
                    bw + ((2 * pr) * 2 + (c >> 1)) * 4 + (c & 1) * 2;
                const uint32_t* bO =
                    bw + ((2 * pr + 1) * 2 + (c >> 1)) * 4 + (c & 1) * 2;
                mma_f16(accE, a, bE);
                mma_f16(accO, a, bO);
            }
            const int c = col0 + wn * 64 + pr * 16 + 4 * tig;
            const float4 ys4 = *reinterpret_cast<const float4*>(&g_ys[c]);
            float4 v0, v1;
            v0.x = epi(accE[0], xs0 + ys4.x);
            v0.y = epi(accE[1], xs0 + ys4.y);
            v0.z = epi(accO[0], xs0 + ys4.z);
            v0.w = epi(accO[1], xs0 + ys4.w);
            v1.x = epi(accE[2], xs1 + ys4.x);
            v1.y = epi(accE[3], xs1 + ys4.y);
            v1.z = epi(accO[2], xs1 + ys4.z);
            v1.w = epi(accO[3], xs1 + ys4.w);
            __stcs(reinterpret_cast<float4*>(out + (size_t)rbase * N + c), v0);
            __stcs(reinterpret_cast<float4*>(out + (size_t)(rbase + 8) * N + c), v1);
        }
    }
}

// ---------------------------------------------------------------------------
extern "C" void kernel_launch(void* const* d_in, const int* in_sizes, int n_in,
                              void* d_out, int out_size) {
    const float* A = (const float*)d_in[0];  // data        [M, 64]
    const float* B = (const float*)d_in[1];  // support_vec [N, 64]
    float* out     = (float*)d_out;          // [M, N]

    const int M = in_sizes[0] / D;           // 8192
    const int N = in_sizes[1] / D;           // 8192

    prep_kernel<<<(M + 31) / 32 * 2, 256>>>(A, B, M);

    dim3 grid(N / BN, M / BM);
    rbf_f16_kernel<<<grid, 256>>>(out, N);
}

// round 16
// speedup vs baseline: 1.1221x; 1.0071x over previous
#include <cuda_runtime.h>
#include <cuda_fp16.h>
#include <cstdint>

#define D      64
#define NROWS  8192
#define BM     64
#define BN     256
#define GAMMA  0.015625f
#define LOG2E  1.4426950408889634f
#define TWOGL  (0.03125f * LOG2E)

// ---------------- device scratch: fp16 fragment-layout inputs ----------------
// A (m16n8k16): value(r,k) -> grp=r>>4, chunk=k>>4, lane=(r&7)*4+((k&7)>>1),
//               reg=((r>>3)&1)+2*((k>>3)&1), half=k&1
// B: col-permuted (perm16); value(j,k) -> grp=(j>>4)*2+(p>>3), col=p&7,
//               pair=k>>5, word=((k>>4)&1)*2+((k>>3)&1), lane=col*4+((k&7)>>1)
__device__ float g_xs[NROWS];   // -gamma*log2e*||x||^2
__device__ float g_ys[NROWS];
__device__ __align__(16) __half g_Af[NROWS * D];
__device__ __align__(16) __half g_Bf[NROWS * D];

// ---------------- prep: 4 rows/warp (MLP=4), fragment scatter + norms -------
__global__ void __launch_bounds__(256)
prep_kernel(const float* __restrict__ A, const float* __restrict__ B,
            int rows_each) {
    int half = gridDim.x >> 1;
    int bid  = blockIdx.x;
    bool isB = bid >= half;
    if (isB) bid -= half;

    const int w0   = bid * 32 + (threadIdx.x >> 5) * 4;   // 4 rows per warp
    const int lane = threadIdx.x & 31;                    // k-pair 2*lane,2*lane+1
    const float* src = isB ? B : A;

    float2 f[4];
#pragma unroll
    for (int i = 0; i < 4; i++)
        f[i] = reinterpret_cast<const float2*>(src + (size_t)(w0 + i) * D)[lane];

#pragma unroll
    for (int i = 0; i < 4; i++) {
        __half2 h = __floats2half2_rn(f[i].x, f[i].y);
        int w = w0 + i;
        if (!isB) {
            int grp  = w >> 4;
            int chnk = lane >> 3;
            int ln   = (w & 7) * 4 + (lane & 3);
            int reg  = ((w >> 3) & 1) + 2 * ((lane >> 2) & 1);
            reinterpret_cast<__half2*>(g_Af)[((grp * 4 + chnk) * 32 + ln) * 4 + reg] = h;
        } else {
            int w16  = w & 15;
            int p    = 2 * (w16 >> 2) + (w16 & 1) + 8 * ((w16 >> 1) & 1); // inv perm16
            int grp  = (w >> 4) * 2 + (p >> 3);
            int ln   = (p & 7) * 4 + (lane & 3);
            int pair = lane >> 4;
            int wrd  = ((lane >> 3) & 1) * 2 + ((lane >> 2) & 1);
            reinterpret_cast<__half2*>(g_Bf)[((grp * 2 + pair) * 32 + ln) * 4 + wrd] = h;
        }
    }

    float s[4];
#pragma unroll
    for (int i = 0; i < 4; i++) s[i] = f[i].x * f[i].x + f[i].y * f[i].y;
#pragma unroll
    for (int o = 16; o; o >>= 1)
#pragma unroll
        for (int i = 0; i < 4; i++)
            s[i] += __shfl_xor_sync(0xffffffffu, s[i], o);
    if (lane < 4) {
        float* nrm = isB ? g_ys : g_xs;
        nrm[w0 + lane] = -(GAMMA * LOG2E) * s[lane];
    }
}

// ---------------- fp16 mma / ex2 helpers ----------------
__device__ __forceinline__ void mma_f16(float* d, const uint32_t* a,
                                        const uint32_t* b) {
    asm volatile(
        "mma.sync.aligned.m16n8k16.row.col.f32.f16.f16.f32 "
        "{%0,%1,%2,%3}, {%4,%5,%6,%7}, {%8,%9}, {%0,%1,%2,%3};"
        : "+f"(d[0]), "+f"(d[1]), "+f"(d[2]), "+f"(d[3])
        : "r"(a[0]), "r"(a[1]), "r"(a[2]), "r"(a[3]), "r"(b[0]), "r"(b[1]));
}
__device__ __forceinline__ float epi(float acc, float xy) {
    float r = fminf(fmaf(TWOGL, acc, xy), 0.f);
    asm("ex2.approx.f32 %0, %1;" : "=f"(r) : "f"(r));
    return r;
}

// ---------------- main: fp16 HMMA, 64x64 warp tile, 128-thr CTA, 4 CTA/SM ---
__global__ void __launch_bounds__(128, 4)
rbf_f16_kernel(float* __restrict__ out, int N) {
    const int tid  = threadIdx.x;
    const int lane = tid & 31;
    const int wn   = tid >> 5;    // 0..3 : 64-col slab
    const int gID  = lane >> 2;
    const int tig  = lane & 3;
    const int row0 = blockIdx.y * BM;
    const int col0 = blockIdx.x * BN;

    const uint4* Af = reinterpret_cast<const uint4*>(g_Af);
    const uint4* Bf = reinterpret_cast<const uint4*>(g_Bf);

    // ---- hoist ALL B fragments for this warp's 64-col slab (16 LDG.128) ----
    uint4 bf[16];   // [group(8 cols)][chunk-pair(32 k)]
    {
        const int bgrp0 = (col0 >> 3) + wn * 8;
#pragma unroll
        for (int g = 0; g < 8; g++)
#pragma unroll
            for (int p = 0; p < 2; p++)
                bf[g * 2 + p] = Bf[(size_t)(((bgrp0 + g) * 2 + p) * 32 + lane)];
    }
    const uint32_t* bw = reinterpret_cast<const uint32_t*>(bf);

#pragma unroll
    for (int mt = 0; mt < 4; mt++) {
        // A fragments for this 16-row group (4 LDG.128)
        uint4 af[4];
        const int agrp = (row0 >> 4) + mt;
#pragma unroll
        for (int c = 0; c < 4; c++)
            af[c] = Af[(size_t)((agrp * 4 + c) * 32 + lane)];
        const uint32_t* aw = reinterpret_cast<const uint32_t*>(af);

        const int rbase = row0 + mt * 16 + gID;
        const float xs0 = g_xs[rbase];
        const float xs1 = g_xs[rbase + 8];

#pragma unroll
        for (int pr = 0; pr < 4; pr++) {
            float accE[4] = {0.f, 0.f, 0.f, 0.f};
            float accO[4] = {0.f, 0.f, 0.f, 0.f};
#pragma unroll
            for (int c = 0; c < 4; c++) {   // 4 k-chunks of 16
                const uint32_t* a  = aw + c * 4;
                const uint32_t* bE =
                    bw + ((2 * pr) * 2 + (c >> 1)) * 4 + (c & 1) * 2;
                const uint32_t* bO =
                    bw + ((2 * pr + 1) * 2 + (c >> 1)) * 4 + (c & 1) * 2;
                mma_f16(accE, a, bE);
                mma_f16(accO, a, bO);
            }
            const int c = col0 + wn * 64 + pr * 16 + 4 * tig;
            const float4 ys4 = *reinterpret_cast<const float4*>(&g_ys[c]);
            float4 v0, v1;
            v0.x = epi(accE[0], xs0 + ys4.x);
            v0.y = epi(accE[1], xs0 + ys4.y);
            v0.z = epi(accO[0], xs0 + ys4.z);
            v0.w = epi(accO[1], xs0 + ys4.w);
            v1.x = epi(accE[2], xs1 + ys4.x);
            v1.y = epi(accE[3], xs1 + ys4.y);
            v1.z = epi(accO[2], xs1 + ys4.z);
            v1.w = epi(accO[3], xs1 + ys4.w);
            __stcs(reinterpret_cast<float4*>(out + (size_t)rbase * N + c), v0);
            __stcs(reinterpret_cast<float4*>(out + (size_t)(rbase + 8) * N + c), v1);
        }
    }
}

// ---------------------------------------------------------------------------
extern "C" void kernel_launch(void* const* d_in, const int* in_sizes, int n_in,
                              void* d_out, int out_size) {
    const float* A = (const float*)d_in[0];  // data        [M, 64]
    const float* B = (const float*)d_in[1];  // support_vec [N, 64]
    float* out     = (float*)d_out;          // [M, N]

    const int M = in_sizes[0] / D;           // 8192
    const int N = in_sizes[1] / D;           // 8192

    prep_kernel<<<(M + 31) / 32 * 2, 256>>>(A, B, M);

    dim3 grid(N / BN, M / BM);
    rbf_f16_kernel<<<grid, 128>>>(out, N);
}